// round 2
// baseline (speedup 1.0000x reference)
#include <cuda_runtime.h>

// BP-MLL loss, factorized per row:
//   s_pos = sum_{t==1} exp(-x), s_neg = sum_{t==0} exp(x)
//   loss  = sum_rows s_pos*s_neg / (n_pos*n_neg)
//
// Single fused kernel: per-row block reduction -> g_row_partial, then the
// LAST block to finish (atomic ticket) sums all partials in fixed order
// (bitwise deterministic across graph replays) and writes the scalar.

#define BB 8192
#define LL 10000
#define LL4 (LL / 4)          // 2500 vec4 chunks per row
#define NTHR 256

__device__ float g_row_partial[BB];
__device__ unsigned int g_done_count = 0;   // reset by the elected finisher

__global__ __launch_bounds__(NTHR)
void bpmll_fused_kernel(const float4* __restrict__ x4,
                        const int4*   __restrict__ t4,
                        float* __restrict__ out)
{
    const int row = blockIdx.x;
    const float4* xr = x4 + (size_t)row * LL4;
    const int4*   tr = t4 + (size_t)row * LL4;

    float sp = 0.0f;   // sum exp(-x) over positives
    float sn = 0.0f;   // sum exp(+x) over negatives
    int   np = 0;      // positive count

    // Streaming (evict-first) loads: data is read exactly once.
    #pragma unroll 4
    for (int i = threadIdx.x; i < LL4; i += NTHR) {
        float4 xv = __ldcs(xr + i);
        int4   tv = __ldcs(tr + i);

        {
            float e = __expf(tv.x ? -xv.x : xv.x);
            if (tv.x) { sp += e; np++; } else { sn += e; }
        }
        {
            float e = __expf(tv.y ? -xv.y : xv.y);
            if (tv.y) { sp += e; np++; } else { sn += e; }
        }
        {
            float e = __expf(tv.z ? -xv.z : xv.z);
            if (tv.z) { sp += e; np++; } else { sn += e; }
        }
        {
            float e = __expf(tv.w ? -xv.w : xv.w);
            if (tv.w) { sp += e; np++; } else { sn += e; }
        }
    }

    // Warp reduction
    #pragma unroll
    for (int off = 16; off > 0; off >>= 1) {
        sp += __shfl_down_sync(0xFFFFFFFFu, sp, off);
        sn += __shfl_down_sync(0xFFFFFFFFu, sn, off);
        np += __shfl_down_sync(0xFFFFFFFFu, np, off);
    }

    __shared__ float s_sp[NTHR / 32];
    __shared__ float s_sn[NTHR / 32];
    __shared__ int   s_np[NTHR / 32];
    __shared__ bool  s_is_last;

    const int lane = threadIdx.x & 31;
    const int wid  = threadIdx.x >> 5;
    if (lane == 0) { s_sp[wid] = sp; s_sn[wid] = sn; s_np[wid] = np; }
    __syncthreads();

    if (wid == 0) {
        sp = (lane < NTHR / 32) ? s_sp[lane] : 0.0f;
        sn = (lane < NTHR / 32) ? s_sn[lane] : 0.0f;
        np = (lane < NTHR / 32) ? s_np[lane] : 0;
        #pragma unroll
        for (int off = (NTHR / 64); off > 0; off >>= 1) {
            sp += __shfl_down_sync(0xFFFFFFFFu, sp, off);
            sn += __shfl_down_sync(0xFFFFFFFFu, sn, off);
            np += __shfl_down_sync(0xFFFFFFFFu, np, off);
        }
        if (lane == 0) {
            const float k = (float)np * (float)(LL - np);
            g_row_partial[row] = sp * sn / k;
            __threadfence();  // make partial visible before the ticket
            unsigned int ticket = atomicAdd(&g_done_count, 1u);
            s_is_last = (ticket == BB - 1);
        }
    }
    __syncthreads();

    // Last block: deterministic fixed-order reduction of all partials.
    if (s_is_last) {
        float s = 0.0f;
        for (int i = threadIdx.x; i < BB; i += NTHR)
            s += g_row_partial[i];

        #pragma unroll
        for (int off = 16; off > 0; off >>= 1)
            s += __shfl_down_sync(0xFFFFFFFFu, s, off);

        __shared__ float s_fin[NTHR / 32];
        if (lane == 0) s_fin[wid] = s;
        __syncthreads();

        if (wid == 0) {
            s = (lane < NTHR / 32) ? s_fin[lane] : 0.0f;
            #pragma unroll
            for (int off = (NTHR / 64); off > 0; off >>= 1)
                s += __shfl_down_sync(0xFFFFFFFFu, s, off);
            if (lane == 0) {
                out[0] = s;
                g_done_count = 0;   // reset for next (graph-replayed) launch
            }
        }
    }
}

extern "C" void kernel_launch(void* const* d_in, const int* in_sizes, int n_in,
                              void* d_out, int out_size)
{
    const float4* x4 = (const float4*)d_in[0];
    const int4*   t4 = (const int4*)d_in[1];
    float* out = (float*)d_out;

    bpmll_fused_kernel<<<BB, NTHR>>>(x4, t4, out);
}